// round 17
// baseline (speedup 1.0000x reference)
#include <cuda_runtime.h>
#include <cuda_fp16.h>
#include <cuda_bf16.h>
#include <cstdint>

#define NUM_NODES 100000
#define EMBED_DIM 64
#define NUM_EDGES 3200000
#define NUM_LAYERS 3

// Padded CSR: fixed slots per node. deg ~ Poisson(32); P(deg >= 96) ~ 1e-18
// per node, so 96 slots never overflow on any realistic draw (clamp-guarded
// anyway). 96*4B = 384B per row -> rows are 128B-aligned.
#define SLOTS 96

// ---------------- scratch (device globals; no runtime allocation) ----------------
__device__ int    g_is64;                // 1 if edge_index really is int64
__device__ int    g_cnt[NUM_NODES];      // per-node degree counter (needs zeroing)
__device__ float  g_dinv[NUM_NODES];
__device__ int    g_csr_src[(size_t)NUM_NODES * SLOTS];
// fp16 ping-pong propagation state: y = dinv * x, stored as half2 pairs
__device__ __half2 g_y0[(size_t)NUM_NODES * (EMBED_DIM / 2)];
__device__ __half2 g_y1[(size_t)NUM_NODES * (EMBED_DIM / 2)];

// ---------------- helpers ----------------

// Fetch edge endpoint `e` of row `row` (0=src, 1=dst), honoring detected dtype.
// Returns -1 if out of range (defensive: surface as rel_err, never crash).
__device__ __forceinline__ int load_idx(const void* ei, int row, int e) {
    long long v;
    if (g_is64) {
        v = ((const long long*)ei)[(size_t)row * NUM_EDGES + e];
    } else {
        v = ((const int*)ei)[(size_t)row * NUM_EDGES + e];
    }
    if ((unsigned long long)v >= (unsigned long long)NUM_NODES) return -1;
    return (int)v;
}

// ---------------- kernels ----------------

// Fused: dtype detect (thread 0) + zero the counters (all threads).
__global__ void k_init(const void* ei) {
    int i = blockIdx.x * blockDim.x + threadIdx.x;
    if (i == 0) {
        const unsigned long long* p = (const unsigned long long*)ei;
        int all_hi_zero = 1;
        for (int k = 0; k < 256; k++) {
            if ((p[k] >> 32) != 0ull) { all_hi_zero = 0; break; }
        }
        g_is64 = all_hi_zero;
    }
    if (i < NUM_NODES) g_cnt[i] = 0;
}

// Single-pass padded-CSR scatter: no histogram, no prefix scan.
// Scalar, 1 edge per thread (R11-proven access shape).
__global__ void k_scatter(const void* __restrict__ ei) {
    int e = blockIdx.x * blockDim.x + threadIdx.x;
    if (e < NUM_EDGES) {
        int s = load_idx(ei, 0, e);
        int d = load_idx(ei, 1, e);
        if (s >= 0 && d >= 0) {
            int pos = atomicAdd(&g_cnt[d], 1);
            if (pos < SLOTS) g_csr_src[(size_t)d * SLOTS + pos] = s;
        }
    }
}

// Fused dinv + layer-0 prescale: one thread per half2 element (3.2M threads).
// dinv computed from cnt per-thread (cnt[node] broadcast-cached); the row's
// first thread also writes g_dinv for the SpMM epilogues.
__global__ void k_dinv_prescale(const float* __restrict__ emb) {
    int e = blockIdx.x * blockDim.x + threadIdx.x;
    if (e < NUM_NODES * (EMBED_DIM / 2)) {
        int node = e >> 5;
        int d = g_cnt[node];
        float sc = (d > 0) ? rsqrtf((float)d) : 0.0f;
        if ((e & 31) == 0) g_dinv[node] = sc;
        float2 v = ((const float2*)emb)[e];
        g_y0[e] = __floats2half2_rn(sc * v.x, sc * v.y);
    }
}

// SpMM, quad-edge scheme: one warp per dst row. 4 groups of 8 lanes; each lane
// loads a uint4 (4 half2 = 16B), so one group fetches a full 128B row -> per
// step the warp serves 4 edges with 1 LDG.128 + 1 SHFL + 4 HADD2. In-batch
// accumulation in fp16 (chain <= 8), flushed to fp32 per 32-edge batch.
// Cross-group merge via shfl_xor(8,16); lanes 0-7 do the float4 epilogue.
//   acc[d] = Σ y[src]; x_next = dinv*acc; out += x_next/4; y_next = dinv*x_next
__global__ void k_spmm(const float* __restrict__ emb,
                       float* __restrict__ out,
                       int layer) {
    int row = blockIdx.x * (blockDim.x >> 5) + (threadIdx.x >> 5);
    if (row >= NUM_NODES) return;
    int lane  = threadIdx.x & 31;
    int group = lane >> 3;               // 0..3: which edge in each 4-pack
    int sub   = lane & 7;                // uint4 slot within the 128B row

    const uint4* yv    = (const uint4*)((layer == 1) ? g_y1 : g_y0);
    __half2*     y_out = (layer == 0) ? g_y1 : g_y0;

    int deg = g_cnt[row];
    if (deg > SLOTS) deg = SLOTS;
    int beg = row * SLOTS;
    int end = beg + deg;

    float acc[8] = {0.f, 0.f, 0.f, 0.f, 0.f, 0.f, 0.f, 0.f};
    for (int b = beg; b < end; b += 32) {
        int n = end - b;
        if (n > 32) n = 32;
        __half2 a0 = __float2half2_rn(0.f);
        __half2 a1 = a0, a2 = a0, a3 = a0;
        if (n == 32) {
            int s = g_csr_src[b + lane];
            #pragma unroll
            for (int k = 0; k < 8; ++k) {
                int sj = __shfl_sync(0xffffffffu, s, 4 * k + group);
                uint4 hv = yv[(size_t)sj * 8 + sub];
                a0 = __hadd2(a0, *(const __half2*)&hv.x);
                a1 = __hadd2(a1, *(const __half2*)&hv.y);
                a2 = __hadd2(a2, *(const __half2*)&hv.z);
                a3 = __hadd2(a3, *(const __half2*)&hv.w);
            }
        } else {
            int s = (lane < n) ? g_csr_src[b + lane] : -1;
            int steps = (n + 3) >> 2;
            for (int k = 0; k < steps; ++k) {
                int sj = __shfl_sync(0xffffffffu, s, 4 * k + group);
                if (sj >= 0) {
                    uint4 hv = yv[(size_t)sj * 8 + sub];
                    a0 = __hadd2(a0, *(const __half2*)&hv.x);
                    a1 = __hadd2(a1, *(const __half2*)&hv.y);
                    a2 = __hadd2(a2, *(const __half2*)&hv.z);
                    a3 = __hadd2(a3, *(const __half2*)&hv.w);
                }
            }
        }
        float2 f;
        f = __half22float2(a0); acc[0] += f.x; acc[1] += f.y;
        f = __half22float2(a1); acc[2] += f.x; acc[3] += f.y;
        f = __half22float2(a2); acc[4] += f.x; acc[5] += f.y;
        f = __half22float2(a3); acc[6] += f.x; acc[7] += f.y;
    }

    // merge the 4 groups' partial sums (same cols, lanes differing in bits 3-4)
    #pragma unroll
    for (int i = 0; i < 8; ++i) {
        acc[i] += __shfl_xor_sync(0xffffffffu, acc[i], 8);
        acc[i] += __shfl_xor_sync(0xffffffffu, acc[i], 16);
    }

    float di = g_dinv[row];

    if (lane < 8) {                      // lane == sub owns cols 8*sub..8*sub+7
        float xn[8];
        #pragma unroll
        for (int i = 0; i < 8; ++i) xn[i] = di * acc[i];

        if (layer != 2) {                // last layer's y is never read
            __half2 h0 = __floats2half2_rn(di * xn[0], di * xn[1]);
            __half2 h1 = __floats2half2_rn(di * xn[2], di * xn[3]);
            __half2 h2 = __floats2half2_rn(di * xn[4], di * xn[5]);
            __half2 h3 = __floats2half2_rn(di * xn[6], di * xn[7]);
            uint4 hv;
            hv.x = *(const unsigned*)&h0;
            hv.y = *(const unsigned*)&h1;
            hv.z = *(const unsigned*)&h2;
            hv.w = *(const unsigned*)&h3;
            ((uint4*)y_out)[(size_t)row * 8 + lane] = hv;
        }

        float4* op = (float4*)(out + (size_t)row * EMBED_DIM) + lane * 2;
        const float inv = 1.0f / (NUM_LAYERS + 1);
        if (layer == 0) {
            const float4* ep = (const float4*)(emb + (size_t)row * EMBED_DIM) + lane * 2;
            float4 e0 = ep[0], e1 = ep[1];
            op[0] = make_float4(inv * (e0.x + xn[0]), inv * (e0.y + xn[1]),
                                inv * (e0.z + xn[2]), inv * (e0.w + xn[3]));
            op[1] = make_float4(inv * (e1.x + xn[4]), inv * (e1.y + xn[5]),
                                inv * (e1.z + xn[6]), inv * (e1.w + xn[7]));
        } else {
            float4 p0 = op[0], p1 = op[1];
            op[0] = make_float4(p0.x + inv * xn[0], p0.y + inv * xn[1],
                                p0.z + inv * xn[2], p0.w + inv * xn[3]);
            op[1] = make_float4(p1.x + inv * xn[4], p1.y + inv * xn[5],
                                p1.z + inv * xn[6], p1.w + inv * xn[7]);
        }
    }
}

// ---------------- launch ----------------

extern "C" void kernel_launch(void* const* d_in, const int* in_sizes, int n_in,
                              void* d_out, int out_size) {
    const float* emb = (const float*)d_in[0];
    const void*  ei  = d_in[1];          // int32 or int64 — detected on device
    float*       out = (float*)d_out;

    const int TB = 256;
    const int node_blocks = (NUM_NODES + TB - 1) / TB;
    const int edge_blocks = (NUM_EDGES + TB - 1) / TB;
    const int pre_elems   = NUM_NODES * (EMBED_DIM / 2);

    k_init<<<node_blocks, TB>>>(ei);
    k_scatter<<<edge_blocks, TB>>>(ei);
    k_dinv_prescale<<<(pre_elems + TB - 1) / TB, TB>>>(emb);

    const int WPB = TB / 32;                                   // 8 warps/block
    const int spmm_blocks = (NUM_NODES + WPB - 1) / WPB;       // 12500

    k_spmm<<<spmm_blocks, TB>>>(emb, out, 0);
    k_spmm<<<spmm_blocks, TB>>>(emb, out, 1);
    k_spmm<<<spmm_blocks, TB>>>(emb, out, 2);
}